// round 7
// baseline (speedup 1.0000x reference)
#include <cuda_runtime.h>

// SampleQueryExtractionLayer: bilinear-style 4-tap gather.
// features: [B=4, N=4096(=64x64), C=256] fp32; query_points: [4,8,256,2];
// out: [8192, 256] fp32.
//
// Latency-chain-optimized single-wave layout: 2048 blocks x 128 threads;
// each 64-thread group owns queries g and g+4096, processed sequentially so
// gather data registers are reused. BOTH query-point loads and BOTH address
// chains (F2I + IMAD) are hoisted to the top, so query 1's four gathers can
// issue immediately behind query 0's. Weight math (incl. MUFU.RCP) stays off
// the address path and overlaps the gather latency.

#define EPS_F 0.0001f

__device__ __forceinline__ const float4* tap_base(const float* __restrict__ feat,
                                                  float2 p, int g, int c4,
                                                  int& y0i, int& x0i)
{
    const int y0 = __float2int_rd(p.x);
    const int x0 = __float2int_rd(p.y);
    y0i = y0; x0i = x0;
    const int b = g >> 11;                        // 2048 queries per batch
    return (const float4*)feat + (size_t)(b * 4096 + y0 * 64 + x0) * 64 + c4;
}

__device__ __forceinline__ float4 blend(const float4* r00, float2 p, int y0, int x0)
{
    // 4 independent gathers, issued as early as possible.
    const float4 f00 = __ldg(r00);
    const float4 f01 = __ldg(r00 + 64);           // (y0, x0+1)
    const float4 f10 = __ldg(r00 + 64 * 64);      // (y0+1, x0)
    const float4 f11 = __ldg(r00 + 64 * 65);      // (y0+1, x0+1)

    const float dy = p.x - (float)y0;
    const float dx = p.y - (float)x0;
    const float m00 = fmaxf(0.f, 1.f - (dy + dx)       + EPS_F);
    const float m01 = fmaxf(0.f, 1.f - (dy + 1.f - dx) + EPS_F);
    const float m10 = fmaxf(0.f, 1.f - (1.f - dy + dx) + EPS_F);
    const float m11 = fmaxf(0.f, 1.f - (2.f - dy - dx) + EPS_F);
    const float w00 = m00 * m00;
    const float w01 = m01 * m01;
    const float w10 = m10 * m10;
    const float w11 = m11 * m11;
    const float inv = __fdividef(1.f, w00 + w01 + w10 + w11 + EPS_F);

    float4 acc;
    acc.x = (w00*f00.x + w01*f01.x + w10*f10.x + w11*f11.x) * inv;
    acc.y = (w00*f00.y + w01*f01.y + w10*f10.y + w11*f11.y) * inv;
    acc.z = (w00*f00.z + w01*f01.z + w10*f10.z + w11*f11.z) * inv;
    acc.w = (w00*f00.w + w01*f01.w + w10*f10.w + w11*f11.w) * inv;
    return acc;
}

__global__ __launch_bounds__(128)
void sqe_kernel(const float* __restrict__ feat,
                const float* __restrict__ qp,
                float* __restrict__ out)
{
    const int tid = threadIdx.x;
    const int grp = blockIdx.x * 2 + (tid >> 6);   // 0..4095
    const int c4  = tid & 63;

    const int q0 = grp;                            // batches 0-1
    const int q1 = grp + 4096;                     // batches 2-3

    // Hop 1: both query points in flight immediately.
    const float2 p0 = __ldg(((const float2*)qp) + q0);
    const float2 p1 = __ldg(((const float2*)qp) + q1);

    // Both address chains resolved up front (F2I + IMAD only).
    int y0a, x0a, y0b, x0b;
    const float4* rA = tap_base(feat, p0, q0, c4, y0a, x0a);
    const float4* rB = tap_base(feat, p1, q1, c4, y0b, x0b);

    // Query 0: gathers issue; weight math overlaps them.
    const float4 acc0 = blend(rA, p0, y0a, x0a);
    __stcs(((float4*)out) + (size_t)q0 * 64 + c4, acc0);

    // Query 1: address already computed, gathers issue back-to-back.
    const float4 acc1 = blend(rB, p1, y0b, x0b);
    __stcs(((float4*)out) + (size_t)q1 * 64 + c4, acc1);
}

extern "C" void kernel_launch(void* const* d_in, const int* in_sizes, int n_in,
                              void* d_out, int out_size)
{
    (void)in_sizes; (void)n_in; (void)out_size;
    const float* feat = (const float*)d_in[0];
    const float* qp   = (const float*)d_in[1];
    float* out        = (float*)d_out;

    // 4096 query-groups, 2 per 128-thread block -> 2048 blocks, single wave.
    sqe_kernel<<<2048, 128>>>(feat, qp, out);
}